// round 1
// baseline (speedup 1.0000x reference)
#include <cuda_runtime.h>
#include <cstdint>

#define Bsz   4
#define Cc    256
#define CE    64
#define Tt    16
#define Hh    56
#define Ww    56
#define HW    3136        // 56*56
#define THW   50176       // 16*3136
#define KK    7
#define Gg    4
#define K2G   196
#define EPSI  1e-5f

// Scratch (device globals: allocation-free rule)
__device__ float g_xenc[(size_t)Bsz * CE * THW];     // 12,845,056 floats
__device__ float g_xcorr[(size_t)Bsz * K2G * THW];   // 39,337,984 floats

typedef unsigned long long ull;

__device__ __forceinline__ void ffma2(ull& d, ull a, ull b) {
    asm("fma.rn.f32x2 %0, %1, %2, %0;" : "+l"(d) : "l"(a), "l"(b));
}
__device__ __forceinline__ ull pack2(float x) {
    ull r;
    unsigned u = __float_as_uint(x);
    asm("mov.b64 %0, {%1, %1};" : "=l"(r) : "r"(u));
    return r;
}
__device__ __forceinline__ float2 unpack2(ull v) {
    unsigned lo, hi;
    asm("mov.b64 {%0, %1}, %2;" : "=r"(lo), "=r"(hi) : "l"(v));
    return make_float2(__uint_as_float(lo), __uint_as_float(hi));
}

// ---------------------------------------------------------------------------
// Kernel 1: enc 1x1 conv (GEMM 64x256 @ 256xTHW per batch) + BN + ReLU
// grid: (392 n-tiles, 4 batches), block 256
// BM=64 (all CE), BN=128, BK=16, thread tile 4m x 8n (as 4x4 f32x2 pairs)
// ---------------------------------------------------------------------------
__global__ void __launch_bounds__(256) enc_kernel(
    const float* __restrict__ x, const float* __restrict__ w,
    const float* __restrict__ eg, const float* __restrict__ eb,
    const float* __restrict__ em, const float* __restrict__ ev)
{
    const int n0 = blockIdx.x * 128;
    const int b  = blockIdx.y;
    __shared__ float As[16][68];    // [k][m], padded
    __shared__ float Bs[16][128];   // [k][n]

    const int t  = threadIdx.x;
    const int tx = t & 15;          // n group (8 cols each)
    const int ty = t >> 4;          // m group (4 rows each)

    ull acc2[4][4];
    #pragma unroll
    for (int i = 0; i < 4; i++)
        #pragma unroll
        for (int j = 0; j < 4; j++) acc2[i][j] = 0ull;

    const float* xb = x + (size_t)b * Cc * THW;

    for (int k0 = 0; k0 < Cc; k0 += 16) {
        // Load A tile: enc_w[m][k0..k0+15], 64x16
        {
            int m  = t >> 2;
            int kk = (t & 3) * 4;
            float4 av = *reinterpret_cast<const float4*>(w + m * Cc + k0 + kk);
            As[kk + 0][m] = av.x; As[kk + 1][m] = av.y;
            As[kk + 2][m] = av.z; As[kk + 3][m] = av.w;
        }
        // Load B tile: x[c=k0+kk][n0+nn], 16x128 as float4
        {
            int idx = t;
            #pragma unroll
            for (int r = 0; r < 2; r++, idx += 256) {
                int kk = idx >> 5;
                int nn = (idx & 31) * 4;
                float4 bv = *reinterpret_cast<const float4*>(
                    xb + (size_t)(k0 + kk) * THW + n0 + nn);
                *reinterpret_cast<float4*>(&Bs[kk][nn]) = bv;
            }
        }
        __syncthreads();

        #pragma unroll
        for (int kk = 0; kk < 16; kk++) {
            float4 av = *reinterpret_cast<const float4*>(&As[kk][ty * 4]);
            const ull* bp = reinterpret_cast<const ull*>(&Bs[kk][tx * 8]);
            ull b0 = bp[0], b1 = bp[1], b2 = bp[2], b3 = bp[3];
            float am[4] = {av.x, av.y, av.z, av.w};
            #pragma unroll
            for (int i = 0; i < 4; i++) {
                ull a2 = pack2(am[i]);
                ffma2(acc2[i][0], a2, b0);
                ffma2(acc2[i][1], a2, b1);
                ffma2(acc2[i][2], a2, b2);
                ffma2(acc2[i][3], a2, b3);
            }
        }
        __syncthreads();
    }

    // Epilogue: BN + ReLU, write x_enc
    const int nb = n0 + tx * 8;
    #pragma unroll
    for (int i = 0; i < 4; i++) {
        int ce = ty * 4 + i;
        float inv  = eg[ce] * rsqrtf(ev[ce] + EPSI);
        float bias = eb[ce] - em[ce] * inv;
        float* op = g_xenc + (size_t)b * CE * THW + (size_t)ce * THW + nb;
        #pragma unroll
        for (int j = 0; j < 4; j++) {
            float2 v = unpack2(acc2[i][j]);
            float r0 = fmaxf(v.x * inv + bias, 0.f);
            float r1 = fmaxf(v.y * inv + bias, 0.f);
            *reinterpret_cast<float2*>(op + j * 2) = make_float2(r0, r1);
        }
    }
}

// ---------------------------------------------------------------------------
// Kernel 2: weighted correlation.
// x_corr[b, tap*4+g, t, h, w] =
//   (1/16) * sum_{ce in group g} fw[ce,t,ky,kx] * x1[ce,h,w] * x2[ce,h+ky-3,w+kx-3]
// x1 = x_enc at t-1 (clamped), x2 = x_enc at t (zero-padded spatially).
// grid: (14 h-tiles of 4 rows, 16 t, 16 b*4+g), block 224 (= 4x56 pixels)
// Channels processed in 2 chunks of 8 to stay under 48KB static smem.
// ---------------------------------------------------------------------------
__global__ void __launch_bounds__(224) corr_kernel(const float* __restrict__ fw)
{
    const int h0 = blockIdx.x * 4;
    const int tt = blockIdx.y;
    const int b  = blockIdx.z >> 2;
    const int g  = blockIdx.z & 3;

    __shared__ float x1s[8][4][56];
    __shared__ float x2s[8][10][62];
    __shared__ float ws[8][49];

    const int tid = threadIdx.x;
    const int py = tid / 56;
    const int px = tid % 56;

    float acc[49];
    #pragma unroll
    for (int i = 0; i < 49; i++) acc[i] = 0.f;

    const int t1 = (tt == 0) ? 0 : tt - 1;
    const float* x1base = g_xenc + (size_t)b * CE * THW + (size_t)t1 * HW;
    const float* x2base = g_xenc + (size_t)b * CE * THW + (size_t)tt * HW;

    for (int chunk = 0; chunk < 2; chunk++) {
        const int ce0 = g * 16 + chunk * 8;

        // weights for this t: 8 x 49
        for (int i = tid; i < 8 * 49; i += 224) {
            int ce = i / 49, tap = i % 49;
            ws[ce][tap] = fw[((size_t)(ce0 + ce) * Tt + tt) * 49 + tap];
        }
        // x1 tile: 8 x 4 x 56 (each thread loads its pixel for all 8 ch)
        #pragma unroll
        for (int ce = 0; ce < 8; ce++) {
            x1s[ce][py][px] =
                x1base[(size_t)(ce0 + ce) * THW + (h0 + py) * Ww + px];
        }
        // x2 halo tile: 8 x 10 x 62, zero-padded
        for (int i = tid; i < 8 * 620; i += 224) {
            int ce = i / 620, p = i % 620;
            int r = p / 62, c = p % 62;
            int hy = h0 + r - 3, wx = c - 3;
            float v = 0.f;
            if (hy >= 0 && hy < Hh && wx >= 0 && wx < Ww)
                v = x2base[(size_t)(ce0 + ce) * THW + hy * Ww + wx];
            x2s[ce][r][c] = v;
        }
        __syncthreads();

        for (int ce = 0; ce < 8; ce++) {
            float x1v = x1s[ce][py][px];
            #pragma unroll
            for (int ky = 0; ky < 7; ky++) {
                #pragma unroll
                for (int kx = 0; kx < 7; kx++) {
                    acc[ky * 7 + kx] +=
                        ws[ce][ky * 7 + kx] * x1v * x2s[ce][py + ky][px + kx];
                }
            }
        }
        __syncthreads();
    }

    float* outb = g_xcorr + (size_t)b * K2G * THW + (size_t)tt * HW
                  + (h0 + py) * Ww + px;
    #pragma unroll
    for (int tap = 0; tap < 49; tap++)
        outb[(size_t)(tap * 4 + g) * THW] = acc[tap] * (1.f / 16.f);
}

// ---------------------------------------------------------------------------
// Kernel 3: dec 1x1 conv (GEMM 256x196 @ 196xTHW per batch) + BN + residual + ReLU
// grid: (392 n-tiles, 2 m-tiles, 4 batches), block 256
// BM=128, BN=128, BK=16, thread tile 8m x 8n (8x4 f32x2 pairs)
// ---------------------------------------------------------------------------
__global__ void __launch_bounds__(256) dec_kernel(
    const float* __restrict__ x, const float* __restrict__ dw,
    const float* __restrict__ dg, const float* __restrict__ db,
    const float* __restrict__ dm, const float* __restrict__ dv,
    float* __restrict__ out)
{
    const int n0 = blockIdx.x * 128;
    const int m0 = blockIdx.y * 128;
    const int b  = blockIdx.z;

    __shared__ float As[16][132];   // [k][m], padded
    __shared__ float Bs[16][128];   // [k][n]

    const int t  = threadIdx.x;
    const int tx = t & 15;          // n group
    const int ty = t >> 4;          // m group

    ull acc2[8][4];
    #pragma unroll
    for (int i = 0; i < 8; i++)
        #pragma unroll
        for (int j = 0; j < 4; j++) acc2[i][j] = 0ull;

    const float* xcb = g_xcorr + (size_t)b * K2G * THW;

    for (int k0 = 0; k0 < K2G; k0 += 16) {   // 13 iters, last partial
        // Load A tile: dec_w[m0+m][k0..k0+15], zero-fill k >= 196
        {
            int m  = t >> 1;
            int kb = (t & 1) * 8;
            #pragma unroll
            for (int i = 0; i < 8; i++) {
                int k = k0 + kb + i;
                As[kb + i][m] = (k < K2G) ? dw[(m0 + m) * K2G + k] : 0.f;
            }
        }
        // Load B tile: x_corr[k][n], zero-fill k >= 196
        {
            int idx = t;
            #pragma unroll
            for (int r = 0; r < 2; r++, idx += 256) {
                int kk = idx >> 5;
                int nn = (idx & 31) * 4;
                float4 bv;
                if (k0 + kk < K2G)
                    bv = *reinterpret_cast<const float4*>(
                        xcb + (size_t)(k0 + kk) * THW + n0 + nn);
                else
                    bv = make_float4(0.f, 0.f, 0.f, 0.f);
                *reinterpret_cast<float4*>(&Bs[kk][nn]) = bv;
            }
        }
        __syncthreads();

        #pragma unroll
        for (int kk = 0; kk < 16; kk++) {
            float4 a0 = *reinterpret_cast<const float4*>(&As[kk][ty * 8]);
            float4 a1 = *reinterpret_cast<const float4*>(&As[kk][ty * 8 + 4]);
            const ull* bp = reinterpret_cast<const ull*>(&Bs[kk][tx * 8]);
            ull b0 = bp[0], b1 = bp[1], b2 = bp[2], b3 = bp[3];
            float am[8] = {a0.x, a0.y, a0.z, a0.w, a1.x, a1.y, a1.z, a1.w};
            #pragma unroll
            for (int i = 0; i < 8; i++) {
                ull a2 = pack2(am[i]);
                ffma2(acc2[i][0], a2, b0);
                ffma2(acc2[i][1], a2, b1);
                ffma2(acc2[i][2], a2, b2);
                ffma2(acc2[i][3], a2, b3);
            }
        }
        __syncthreads();
    }

    // Epilogue: BN + residual + ReLU
    const int nb = n0 + tx * 8;
    #pragma unroll
    for (int i = 0; i < 8; i++) {
        int o = m0 + ty * 8 + i;
        float inv  = dg[o] * rsqrtf(dv[o] + EPSI);
        float bias = db[o] - dm[o] * inv;
        const float* xr = x + (size_t)b * Cc * THW + (size_t)o * THW + nb;
        float*       op = out + (size_t)b * Cc * THW + (size_t)o * THW + nb;
        #pragma unroll
        for (int j = 0; j < 4; j++) {
            float2 v  = unpack2(acc2[i][j]);
            float2 rv = *reinterpret_cast<const float2*>(xr + j * 2);
            float r0 = fmaxf(v.x * inv + bias + rv.x, 0.f);
            float r1 = fmaxf(v.y * inv + bias + rv.y, 0.f);
            *reinterpret_cast<float2*>(op + j * 2) = make_float2(r0, r1);
        }
    }
}

// ---------------------------------------------------------------------------
extern "C" void kernel_launch(void* const* d_in, const int* in_sizes, int n_in,
                              void* d_out, int out_size)
{
    const float* x     = (const float*)d_in[0];
    const float* enc_w = (const float*)d_in[1];
    const float* eg    = (const float*)d_in[2];
    const float* eb    = (const float*)d_in[3];
    const float* em    = (const float*)d_in[4];
    const float* ev    = (const float*)d_in[5];
    const float* fw    = (const float*)d_in[6];
    const float* dw    = (const float*)d_in[7];
    const float* dg    = (const float*)d_in[8];
    const float* db    = (const float*)d_in[9];
    const float* dm    = (const float*)d_in[10];
    const float* dv    = (const float*)d_in[11];
    float* out = (float*)d_out;

    dim3 g1(THW / 128, Bsz);
    enc_kernel<<<g1, 256>>>(x, enc_w, eg, eb, em, ev);

    dim3 g2(Hh / 4, Tt, Bsz * Gg);
    corr_kernel<<<g2, 224>>>(fw);

    dim3 g3(THW / 128, 2, Bsz);
    dec_kernel<<<g3, 256>>>(x, dw, dg, db, dm, dv, out);
}

// round 2
// speedup vs baseline: 1.2763x; 1.2763x over previous
#include <cuda_runtime.h>
#include <cstdint>

#define Bsz   4
#define Cc    256
#define CE    64
#define Tt    16
#define Hh    56
#define Ww    56
#define HW    3136        // 56*56
#define THW   50176       // 16*3136
#define KK    7
#define Gg    4
#define K2G   196
#define EPSI  1e-5f

// Scratch (device globals: allocation-free rule)
__device__ float g_xenc[(size_t)Bsz * CE * THW];
__device__ float g_xcorr[(size_t)Bsz * K2G * THW];

typedef unsigned long long ull;

__device__ __forceinline__ void ffma2(ull& d, ull a, ull b) {
    asm("fma.rn.f32x2 %0, %1, %2, %0;" : "+l"(d) : "l"(a), "l"(b));
}
__device__ __forceinline__ ull pack2(float x) {
    ull r;
    unsigned u = __float_as_uint(x);
    asm("mov.b64 %0, {%1, %1};" : "=l"(r) : "r"(u));
    return r;
}
__device__ __forceinline__ float2 unpack2(ull v) {
    unsigned lo, hi;
    asm("mov.b64 {%0, %1}, %2;" : "=r"(lo), "=r"(hi) : "l"(v));
    return make_float2(__uint_as_float(lo), __uint_as_float(hi));
}
__device__ __forceinline__ void cp_async16(uint32_t smem_addr, const void* gptr, int src_bytes) {
    asm volatile("cp.async.cg.shared.global [%0], [%1], 16, %2;"
                 :: "r"(smem_addr), "l"(gptr), "r"(src_bytes));
}
__device__ __forceinline__ void cp_commit() {
    asm volatile("cp.async.commit_group;");
}
__device__ __forceinline__ void cp_wait0() {
    asm volatile("cp.async.wait_group 0;");
}

// ---------------------------------------------------------------------------
// Kernel 1: enc 1x1 conv (GEMM 64x256 @ 256xTHW per batch) + BN + ReLU
// BM=64, BN=256, BK=16, 256 threads (32 tx x 8 ty), rtile 8m x 8n
// n columns per thread: tx*4 + 128j (j=0,1) -> conflict-free LDS.128
// Double-buffered smem, cp.async for B, reg-staged A.
// ---------------------------------------------------------------------------
__global__ void __launch_bounds__(256, 2) enc_kernel(
    const float* __restrict__ x, const float* __restrict__ w,
    const float* __restrict__ eg, const float* __restrict__ eb,
    const float* __restrict__ em, const float* __restrict__ ev)
{
    const int n0 = blockIdx.x * 256;
    const int b  = blockIdx.y;

    __shared__ float Bs[2][16][256];   // 32 KB
    __shared__ float As[2][16][64];    // 8 KB  [k][m]

    const int t  = threadIdx.x;
    const int tx = t & 31;
    const int ty = t >> 5;             // 0..7, m = ty*8

    ull acc2[8][2][2];
    #pragma unroll
    for (int i = 0; i < 8; i++)
        #pragma unroll
        for (int j = 0; j < 2; j++) { acc2[i][j][0] = 0ull; acc2[i][j][1] = 0ull; }

    const float* xb = x + (size_t)b * Cc * THW;

    // A load indices: 64x16 tile = 1024 floats, 4 per thread (1 float4)
    const int am = t >> 2;             // 0..63
    const int ak = (t & 3) * 4;        // 0,4,8,12

    // B cp.async indices: 16x256 = 1024 x 16B chunks? -> 1024 floats*16 = 16KB,
    // 1024 chunks of 16B, 4 chunks per thread
    // chunk c: kk = c>>6, pos = (c&63)*4
    const int NT = Cc / 16;            // 16 tiles

    // ---- prologue: tile 0 ----
    {
        float4 av = *reinterpret_cast<const float4*>(w + am * Cc + 0 + ak);
        #pragma unroll
        for (int c = t; c < 1024; c += 256) {
            int kk = c >> 6, pos = (c & 63) * 4;
            uint32_t dst = (uint32_t)__cvta_generic_to_shared(&Bs[0][kk][pos]);
            cp_async16(dst, xb + (size_t)kk * THW + n0 + pos, 16);
        }
        cp_commit();
        As[0][ak + 0][am] = av.x; As[0][ak + 1][am] = av.y;
        As[0][ak + 2][am] = av.z; As[0][ak + 3][am] = av.w;
        cp_wait0();
        __syncthreads();
    }

    for (int it = 0; it < NT; it++) {
        const int buf = it & 1;
        float4 av;
        bool more = (it + 1 < NT);
        if (more) {
            int k0n = (it + 1) * 16;
            av = *reinterpret_cast<const float4*>(w + am * Cc + k0n + ak);
            #pragma unroll
            for (int c = t; c < 1024; c += 256) {
                int kk = c >> 6, pos = (c & 63) * 4;
                uint32_t dst = (uint32_t)__cvta_generic_to_shared(&Bs[buf ^ 1][kk][pos]);
                cp_async16(dst, xb + (size_t)(k0n + kk) * THW + n0 + pos, 16);
            }
            cp_commit();
        }

        #pragma unroll
        for (int kk = 0; kk < 16; kk++) {
            float4 a0 = *reinterpret_cast<const float4*>(&As[buf][kk][ty * 8]);
            float4 a1 = *reinterpret_cast<const float4*>(&As[buf][kk][ty * 8 + 4]);
            ulonglong2 b0 = *reinterpret_cast<const ulonglong2*>(&Bs[buf][kk][tx * 4]);
            ulonglong2 b1 = *reinterpret_cast<const ulonglong2*>(&Bs[buf][kk][tx * 4 + 128]);
            float am8[8] = {a0.x, a0.y, a0.z, a0.w, a1.x, a1.y, a1.z, a1.w};
            #pragma unroll
            for (int i = 0; i < 8; i++) {
                ull a2 = pack2(am8[i]);
                ffma2(acc2[i][0][0], a2, b0.x);
                ffma2(acc2[i][0][1], a2, b0.y);
                ffma2(acc2[i][1][0], a2, b1.x);
                ffma2(acc2[i][1][1], a2, b1.y);
            }
        }

        if (more) {
            As[buf ^ 1][ak + 0][am] = av.x; As[buf ^ 1][ak + 1][am] = av.y;
            As[buf ^ 1][ak + 2][am] = av.z; As[buf ^ 1][ak + 3][am] = av.w;
        }
        cp_wait0();
        __syncthreads();
    }

    // Epilogue: BN + ReLU
    #pragma unroll
    for (int i = 0; i < 8; i++) {
        int ce = ty * 8 + i;
        float inv  = eg[ce] * rsqrtf(ev[ce] + EPSI);
        float bias = eb[ce] - em[ce] * inv;
        float* op = g_xenc + (size_t)b * CE * THW + (size_t)ce * THW + n0;
        #pragma unroll
        for (int j = 0; j < 2; j++) {
            float2 v0 = unpack2(acc2[i][j][0]);
            float2 v1 = unpack2(acc2[i][j][1]);
            float4 r;
            r.x = fmaxf(v0.x * inv + bias, 0.f);
            r.y = fmaxf(v0.y * inv + bias, 0.f);
            r.z = fmaxf(v1.x * inv + bias, 0.f);
            r.w = fmaxf(v1.y * inv + bias, 0.f);
            *reinterpret_cast<float4*>(op + tx * 4 + 128 * j) = r;
        }
    }
}

// ---------------------------------------------------------------------------
// Kernel 2: weighted correlation (unchanged from R1)
// ---------------------------------------------------------------------------
__global__ void __launch_bounds__(224) corr_kernel(const float* __restrict__ fw)
{
    const int h0 = blockIdx.x * 4;
    const int tt = blockIdx.y;
    const int b  = blockIdx.z >> 2;
    const int g  = blockIdx.z & 3;

    __shared__ float x1s[8][4][56];
    __shared__ float x2s[8][10][62];
    __shared__ float ws[8][49];

    const int tid = threadIdx.x;
    const int py = tid / 56;
    const int px = tid % 56;

    float acc[49];
    #pragma unroll
    for (int i = 0; i < 49; i++) acc[i] = 0.f;

    const int t1 = (tt == 0) ? 0 : tt - 1;
    const float* x1base = g_xenc + (size_t)b * CE * THW + (size_t)t1 * HW;
    const float* x2base = g_xenc + (size_t)b * CE * THW + (size_t)tt * HW;

    for (int chunk = 0; chunk < 2; chunk++) {
        const int ce0 = g * 16 + chunk * 8;

        for (int i = tid; i < 8 * 49; i += 224) {
            int ce = i / 49, tap = i % 49;
            ws[ce][tap] = fw[((size_t)(ce0 + ce) * Tt + tt) * 49 + tap];
        }
        #pragma unroll
        for (int ce = 0; ce < 8; ce++) {
            x1s[ce][py][px] =
                x1base[(size_t)(ce0 + ce) * THW + (h0 + py) * Ww + px];
        }
        for (int i = tid; i < 8 * 620; i += 224) {
            int ce = i / 620, p = i % 620;
            int r = p / 62, c = p % 62;
            int hy = h0 + r - 3, wx = c - 3;
            float v = 0.f;
            if (hy >= 0 && hy < Hh && wx >= 0 && wx < Ww)
                v = x2base[(size_t)(ce0 + ce) * THW + hy * Ww + wx];
            x2s[ce][r][c] = v;
        }
        __syncthreads();

        for (int ce = 0; ce < 8; ce++) {
            float x1v = x1s[ce][py][px];
            #pragma unroll
            for (int ky = 0; ky < 7; ky++) {
                #pragma unroll
                for (int kx = 0; kx < 7; kx++) {
                    acc[ky * 7 + kx] +=
                        ws[ce][ky * 7 + kx] * x1v * x2s[ce][py + ky][px + kx];
                }
            }
        }
        __syncthreads();
    }

    float* outb = g_xcorr + (size_t)b * K2G * THW + (size_t)tt * HW
                  + (h0 + py) * Ww + px;
    #pragma unroll
    for (int tap = 0; tap < 49; tap++)
        outb[(size_t)(tap * 4 + g) * THW] = acc[tap] * (1.f / 16.f);
}

// ---------------------------------------------------------------------------
// Kernel 3: dec 1x1 conv (GEMM 256x196 @ 196xTHW per batch) + BN + res + ReLU
// BM=128, BN=256, BK=16, 512 threads (32 tx x 16 ty), rtile 8m x 8n
// Double-buffered smem, cp.async B (src-size=0 zero-fill on K tail),
// reg-staged A with bounds predicate.
// ---------------------------------------------------------------------------
__global__ void __launch_bounds__(512, 1) dec_kernel(
    const float* __restrict__ x, const float* __restrict__ dw,
    const float* __restrict__ dg, const float* __restrict__ db,
    const float* __restrict__ dm, const float* __restrict__ dv,
    float* __restrict__ out)
{
    const int n0 = blockIdx.x * 256;
    const int m0 = blockIdx.y * 128;
    const int b  = blockIdx.z;

    __shared__ float Bs[2][16][256];   // 32 KB
    __shared__ float As[2][16][128];   // 16 KB  [k][m]

    const int t  = threadIdx.x;
    const int tx = t & 31;
    const int ty = t >> 5;             // 0..15, m = ty*8

    ull acc2[8][2][2];
    #pragma unroll
    for (int i = 0; i < 8; i++)
        #pragma unroll
        for (int j = 0; j < 2; j++) { acc2[i][j][0] = 0ull; acc2[i][j][1] = 0ull; }

    const float* xcb = g_xcorr + (size_t)b * K2G * THW;

    // A: 128x16 tile = 2048 floats, 4 per thread (1 float4)
    const int am = t >> 2;             // 0..127
    const int ak = (t & 3) * 4;        // 0,4,8,12
    const int NT = (K2G + 15) / 16;    // 13 tiles (last partial: 4 valid rows)

    // ---- prologue: tile 0 (fully valid) ----
    {
        float4 av = *reinterpret_cast<const float4*>(dw + (m0 + am) * K2G + ak);
        #pragma unroll
        for (int c = t; c < 1024; c += 512) {
            int kk = c >> 6, pos = (c & 63) * 4;
            uint32_t dst = (uint32_t)__cvta_generic_to_shared(&Bs[0][kk][pos]);
            cp_async16(dst, xcb + (size_t)kk * THW + n0 + pos, 16);
        }
        cp_commit();
        As[0][ak + 0][am] = av.x; As[0][ak + 1][am] = av.y;
        As[0][ak + 2][am] = av.z; As[0][ak + 3][am] = av.w;
        cp_wait0();
        __syncthreads();
    }

    for (int it = 0; it < NT; it++) {
        const int buf = it & 1;
        float4 av = make_float4(0.f, 0.f, 0.f, 0.f);
        bool more = (it + 1 < NT);
        if (more) {
            int k0n = (it + 1) * 16;
            if (k0n + ak < K2G)   // full float4 valid (K2G % 4 == 0)
                av = *reinterpret_cast<const float4*>(dw + (m0 + am) * K2G + k0n + ak);
            #pragma unroll
            for (int c = t; c < 1024; c += 512) {
                int kk = c >> 6, pos = (c & 63) * 4;
                int sz = (k0n + kk < K2G) ? 16 : 0;
                uint32_t dst = (uint32_t)__cvta_generic_to_shared(&Bs[buf ^ 1][kk][pos]);
                cp_async16(dst, xcb + (size_t)(k0n + kk) * THW + n0 + pos, sz);
            }
            cp_commit();
        }

        #pragma unroll
        for (int kk = 0; kk < 16; kk++) {
            float4 a0 = *reinterpret_cast<const float4*>(&As[buf][kk][ty * 8]);
            float4 a1 = *reinterpret_cast<const float4*>(&As[buf][kk][ty * 8 + 4]);
            ulonglong2 b0 = *reinterpret_cast<const ulonglong2*>(&Bs[buf][kk][tx * 4]);
            ulonglong2 b1 = *reinterpret_cast<const ulonglong2*>(&Bs[buf][kk][tx * 4 + 128]);
            float am8[8] = {a0.x, a0.y, a0.z, a0.w, a1.x, a1.y, a1.z, a1.w};
            #pragma unroll
            for (int i = 0; i < 8; i++) {
                ull a2 = pack2(am8[i]);
                ffma2(acc2[i][0][0], a2, b0.x);
                ffma2(acc2[i][0][1], a2, b0.y);
                ffma2(acc2[i][1][0], a2, b1.x);
                ffma2(acc2[i][1][1], a2, b1.y);
            }
        }

        if (more) {
            As[buf ^ 1][ak + 0][am] = av.x; As[buf ^ 1][ak + 1][am] = av.y;
            As[buf ^ 1][ak + 2][am] = av.z; As[buf ^ 1][ak + 3][am] = av.w;
        }
        cp_wait0();
        __syncthreads();
    }

    // Epilogue: BN + residual + ReLU
    #pragma unroll
    for (int i = 0; i < 8; i++) {
        int o = m0 + ty * 8 + i;
        float inv  = dg[o] * rsqrtf(dv[o] + EPSI);
        float bias = db[o] - dm[o] * inv;
        const float* xr = x + (size_t)b * Cc * THW + (size_t)o * THW + n0;
        float*       op = out + (size_t)b * Cc * THW + (size_t)o * THW + n0;
        #pragma unroll
        for (int j = 0; j < 2; j++) {
            float2 v0 = unpack2(acc2[i][j][0]);
            float2 v1 = unpack2(acc2[i][j][1]);
            float4 rv = *reinterpret_cast<const float4*>(xr + tx * 4 + 128 * j);
            float4 r;
            r.x = fmaxf(v0.x * inv + bias + rv.x, 0.f);
            r.y = fmaxf(v0.y * inv + bias + rv.y, 0.f);
            r.z = fmaxf(v1.x * inv + bias + rv.z, 0.f);
            r.w = fmaxf(v1.y * inv + bias + rv.w, 0.f);
            *reinterpret_cast<float4*>(op + tx * 4 + 128 * j) = r;
        }
    }
}

// ---------------------------------------------------------------------------
extern "C" void kernel_launch(void* const* d_in, const int* in_sizes, int n_in,
                              void* d_out, int out_size)
{
    const float* x     = (const float*)d_in[0];
    const float* enc_w = (const float*)d_in[1];
    const float* eg    = (const float*)d_in[2];
    const float* eb    = (const float*)d_in[3];
    const float* em    = (const float*)d_in[4];
    const float* ev    = (const float*)d_in[5];
    const float* fw    = (const float*)d_in[6];
    const float* dw    = (const float*)d_in[7];
    const float* dg    = (const float*)d_in[8];
    const float* db    = (const float*)d_in[9];
    const float* dm    = (const float*)d_in[10];
    const float* dv    = (const float*)d_in[11];
    float* out = (float*)d_out;

    dim3 g1(THW / 256, Bsz);
    enc_kernel<<<g1, 256>>>(x, enc_w, eg, eb, em, ev);

    dim3 g2(Hh / 4, Tt, Bsz * Gg);
    corr_kernel<<<g2, 224>>>(fw);

    dim3 g3(THW / 256, 2, Bsz);
    dec_kernel<<<g3, 512>>>(x, dw, dg, db, dm, dv, out);
}

// round 3
// speedup vs baseline: 1.2850x; 1.0068x over previous
#include <cuda_runtime.h>
#include <cstdint>

#define Bsz   4
#define Cc    256
#define CE    64
#define Tt    16
#define Hh    56
#define Ww    56
#define HW    3136        // 56*56
#define THW   50176       // 16*3136
#define KK    7
#define Gg    4
#define K2G   196
#define EPSI  1e-5f

// Scratch (device globals: allocation-free rule)
__device__ float g_xenc[(size_t)Bsz * CE * THW];
__device__ float g_xcorr[(size_t)Bsz * K2G * THW];

typedef unsigned long long ull;

__device__ __forceinline__ void ffma2(ull& d, ull a, ull b) {
    asm("fma.rn.f32x2 %0, %1, %2, %0;" : "+l"(d) : "l"(a), "l"(b));
}
__device__ __forceinline__ ull pack2(float x) {
    ull r;
    unsigned u = __float_as_uint(x);
    asm("mov.b64 %0, {%1, %1};" : "=l"(r) : "r"(u));
    return r;
}
__device__ __forceinline__ float2 unpack2(ull v) {
    unsigned lo, hi;
    asm("mov.b64 {%0, %1}, %2;" : "=r"(lo), "=r"(hi) : "l"(v));
    return make_float2(__uint_as_float(lo), __uint_as_float(hi));
}
__device__ __forceinline__ void cp_async16(uint32_t smem_addr, const void* gptr, int src_bytes) {
    asm volatile("cp.async.cg.shared.global [%0], [%1], 16, %2;"
                 :: "r"(smem_addr), "l"(gptr), "r"(src_bytes));
}
__device__ __forceinline__ void cp_commit() {
    asm volatile("cp.async.commit_group;");
}
__device__ __forceinline__ void cp_wait0() {
    asm volatile("cp.async.wait_group 0;");
}

// ---------------------------------------------------------------------------
// Kernel 1: enc 1x1 conv (GEMM 64x256 @ 256xTHW per batch) + BN + ReLU
// BM=64, BN=256, BK=16, 128 threads (16 tx x 8 ty), thread tile 8m x 16n.
// n per thread: tx*4 + 64j (j=0..3). smem demand 96 B/cyc < 128 crossbar.
// ---------------------------------------------------------------------------
__global__ void __launch_bounds__(128, 2) enc_kernel(
    const float* __restrict__ x, const float* __restrict__ w,
    const float* __restrict__ eg, const float* __restrict__ eb,
    const float* __restrict__ em, const float* __restrict__ ev)
{
    const int n0 = blockIdx.x * 256;
    const int b  = blockIdx.y;

    __shared__ float Bs[2][16][256];   // 32 KB
    __shared__ float As[2][16][64];    // 8 KB  [k][m]

    const int t  = threadIdx.x;
    const int tx = t & 15;             // n base = tx*4 + 64j
    const int ty = t >> 4;             // 0..7, m = ty*8

    ull acc[8][8];
    #pragma unroll
    for (int i = 0; i < 8; i++)
        #pragma unroll
        for (int j = 0; j < 8; j++) acc[i][j] = 0ull;

    const float* xb = x + (size_t)b * Cc * THW;

    // A: 64x16 tile = 1024 floats, 8 per thread (2 float4)
    const int am = t >> 1;             // 0..63
    const int ak = (t & 1) * 8;        // 0 or 8
    const int NT = Cc / 16;            // 16 tiles

    // ---- prologue: tile 0 ----
    {
        float4 av0 = *reinterpret_cast<const float4*>(w + am * Cc + ak);
        float4 av1 = *reinterpret_cast<const float4*>(w + am * Cc + ak + 4);
        #pragma unroll
        for (int c = t; c < 1024; c += 128) {
            int kk = c >> 6, pos = (c & 63) * 4;
            uint32_t dst = (uint32_t)__cvta_generic_to_shared(&Bs[0][kk][pos]);
            cp_async16(dst, xb + (size_t)kk * THW + n0 + pos, 16);
        }
        cp_commit();
        As[0][ak + 0][am] = av0.x; As[0][ak + 1][am] = av0.y;
        As[0][ak + 2][am] = av0.z; As[0][ak + 3][am] = av0.w;
        As[0][ak + 4][am] = av1.x; As[0][ak + 5][am] = av1.y;
        As[0][ak + 6][am] = av1.z; As[0][ak + 7][am] = av1.w;
        cp_wait0();
        __syncthreads();
    }

    for (int it = 0; it < NT; it++) {
        const int buf = it & 1;
        float4 av0, av1;
        bool more = (it + 1 < NT);
        if (more) {
            int k0n = (it + 1) * 16;
            av0 = *reinterpret_cast<const float4*>(w + am * Cc + k0n + ak);
            av1 = *reinterpret_cast<const float4*>(w + am * Cc + k0n + ak + 4);
            #pragma unroll
            for (int c = t; c < 1024; c += 128) {
                int kk = c >> 6, pos = (c & 63) * 4;
                uint32_t dst = (uint32_t)__cvta_generic_to_shared(&Bs[buf ^ 1][kk][pos]);
                cp_async16(dst, xb + (size_t)(k0n + kk) * THW + n0 + pos, 16);
            }
            cp_commit();
        }

        #pragma unroll
        for (int kk = 0; kk < 16; kk++) {
            float4 a0 = *reinterpret_cast<const float4*>(&As[buf][kk][ty * 8]);
            float4 a1 = *reinterpret_cast<const float4*>(&As[buf][kk][ty * 8 + 4]);
            ulonglong2 b0 = *reinterpret_cast<const ulonglong2*>(&Bs[buf][kk][tx * 4]);
            ulonglong2 b1 = *reinterpret_cast<const ulonglong2*>(&Bs[buf][kk][tx * 4 + 64]);
            ulonglong2 b2 = *reinterpret_cast<const ulonglong2*>(&Bs[buf][kk][tx * 4 + 128]);
            ulonglong2 b3 = *reinterpret_cast<const ulonglong2*>(&Bs[buf][kk][tx * 4 + 192]);
            float am8[8] = {a0.x, a0.y, a0.z, a0.w, a1.x, a1.y, a1.z, a1.w};
            #pragma unroll
            for (int i = 0; i < 8; i++) {
                ull a2 = pack2(am8[i]);
                ffma2(acc[i][0], a2, b0.x); ffma2(acc[i][1], a2, b0.y);
                ffma2(acc[i][2], a2, b1.x); ffma2(acc[i][3], a2, b1.y);
                ffma2(acc[i][4], a2, b2.x); ffma2(acc[i][5], a2, b2.y);
                ffma2(acc[i][6], a2, b3.x); ffma2(acc[i][7], a2, b3.y);
            }
        }

        if (more) {
            As[buf ^ 1][ak + 0][am] = av0.x; As[buf ^ 1][ak + 1][am] = av0.y;
            As[buf ^ 1][ak + 2][am] = av0.z; As[buf ^ 1][ak + 3][am] = av0.w;
            As[buf ^ 1][ak + 4][am] = av1.x; As[buf ^ 1][ak + 5][am] = av1.y;
            As[buf ^ 1][ak + 6][am] = av1.z; As[buf ^ 1][ak + 7][am] = av1.w;
        }
        cp_wait0();
        __syncthreads();
    }

    // Epilogue: BN + ReLU
    #pragma unroll
    for (int i = 0; i < 8; i++) {
        int ce = ty * 8 + i;
        float inv  = eg[ce] * rsqrtf(ev[ce] + EPSI);
        float bias = eb[ce] - em[ce] * inv;
        float* op = g_xenc + (size_t)b * CE * THW + (size_t)ce * THW + n0;
        #pragma unroll
        for (int j = 0; j < 4; j++) {
            float2 v0 = unpack2(acc[i][2 * j]);
            float2 v1 = unpack2(acc[i][2 * j + 1]);
            float4 r;
            r.x = fmaxf(v0.x * inv + bias, 0.f);
            r.y = fmaxf(v0.y * inv + bias, 0.f);
            r.z = fmaxf(v1.x * inv + bias, 0.f);
            r.w = fmaxf(v1.y * inv + bias, 0.f);
            *reinterpret_cast<float4*>(op + tx * 4 + 64 * j) = r;
        }
    }
}

// ---------------------------------------------------------------------------
// Kernel 2: weighted correlation (unchanged)
// ---------------------------------------------------------------------------
__global__ void __launch_bounds__(224) corr_kernel(const float* __restrict__ fw)
{
    const int h0 = blockIdx.x * 4;
    const int tt = blockIdx.y;
    const int b  = blockIdx.z >> 2;
    const int g  = blockIdx.z & 3;

    __shared__ float x1s[8][4][56];
    __shared__ float x2s[8][10][62];
    __shared__ float ws[8][49];

    const int tid = threadIdx.x;
    const int py = tid / 56;
    const int px = tid % 56;

    float acc[49];
    #pragma unroll
    for (int i = 0; i < 49; i++) acc[i] = 0.f;

    const int t1 = (tt == 0) ? 0 : tt - 1;
    const float* x1base = g_xenc + (size_t)b * CE * THW + (size_t)t1 * HW;
    const float* x2base = g_xenc + (size_t)b * CE * THW + (size_t)tt * HW;

    for (int chunk = 0; chunk < 2; chunk++) {
        const int ce0 = g * 16 + chunk * 8;

        for (int i = tid; i < 8 * 49; i += 224) {
            int ce = i / 49, tap = i % 49;
            ws[ce][tap] = fw[((size_t)(ce0 + ce) * Tt + tt) * 49 + tap];
        }
        #pragma unroll
        for (int ce = 0; ce < 8; ce++) {
            x1s[ce][py][px] =
                x1base[(size_t)(ce0 + ce) * THW + (h0 + py) * Ww + px];
        }
        for (int i = tid; i < 8 * 620; i += 224) {
            int ce = i / 620, p = i % 620;
            int r = p / 62, c = p % 62;
            int hy = h0 + r - 3, wx = c - 3;
            float v = 0.f;
            if (hy >= 0 && hy < Hh && wx >= 0 && wx < Ww)
                v = x2base[(size_t)(ce0 + ce) * THW + hy * Ww + wx];
            x2s[ce][r][c] = v;
        }
        __syncthreads();

        for (int ce = 0; ce < 8; ce++) {
            float x1v = x1s[ce][py][px];
            #pragma unroll
            for (int ky = 0; ky < 7; ky++) {
                #pragma unroll
                for (int kx = 0; kx < 7; kx++) {
                    acc[ky * 7 + kx] +=
                        ws[ce][ky * 7 + kx] * x1v * x2s[ce][py + ky][px + kx];
                }
            }
        }
        __syncthreads();
    }

    float* outb = g_xcorr + (size_t)b * K2G * THW + (size_t)tt * HW
                  + (h0 + py) * Ww + px;
    #pragma unroll
    for (int tap = 0; tap < 49; tap++)
        outb[(size_t)(tap * 4 + g) * THW] = acc[tap] * (1.f / 16.f);
}

// ---------------------------------------------------------------------------
// Kernel 3: dec 1x1 conv (GEMM 256x196 @ 196xTHW per batch) + BN + res + ReLU
// BM=128, BN=256, BK=16, 256 threads (16 tx x 16 ty), thread tile 8m x 16n.
// ---------------------------------------------------------------------------
__global__ void __launch_bounds__(256, 1) dec_kernel(
    const float* __restrict__ x, const float* __restrict__ dw,
    const float* __restrict__ dg, const float* __restrict__ db,
    const float* __restrict__ dm, const float* __restrict__ dv,
    float* __restrict__ out)
{
    const int n0 = blockIdx.x * 256;
    const int m0 = blockIdx.y * 128;
    const int b  = blockIdx.z;

    __shared__ float Bs[2][16][256];   // 32 KB
    __shared__ float As[2][16][128];   // 16 KB  [k][m]

    const int t  = threadIdx.x;
    const int tx = t & 15;
    const int ty = t >> 4;             // 0..15, m = ty*8

    ull acc[8][8];
    #pragma unroll
    for (int i = 0; i < 8; i++)
        #pragma unroll
        for (int j = 0; j < 8; j++) acc[i][j] = 0ull;

    const float* xcb = g_xcorr + (size_t)b * K2G * THW;

    // A: 128x16 tile = 2048 floats, 8 per thread (2 float4)
    const int am = t >> 1;             // 0..127
    const int ak = (t & 1) * 8;        // 0 or 8
    const int NT = (K2G + 15) / 16;    // 13 (last: 4 valid k rows)

    // ---- prologue: tile 0 (fully valid) ----
    {
        float4 av0 = *reinterpret_cast<const float4*>(dw + (m0 + am) * K2G + ak);
        float4 av1 = *reinterpret_cast<const float4*>(dw + (m0 + am) * K2G + ak + 4);
        #pragma unroll
        for (int c = t; c < 1024; c += 256) {
            int kk = c >> 6, pos = (c & 63) * 4;
            uint32_t dst = (uint32_t)__cvta_generic_to_shared(&Bs[0][kk][pos]);
            cp_async16(dst, xcb + (size_t)kk * THW + n0 + pos, 16);
        }
        cp_commit();
        As[0][ak + 0][am] = av0.x; As[0][ak + 1][am] = av0.y;
        As[0][ak + 2][am] = av0.z; As[0][ak + 3][am] = av0.w;
        As[0][ak + 4][am] = av1.x; As[0][ak + 5][am] = av1.y;
        As[0][ak + 6][am] = av1.z; As[0][ak + 7][am] = av1.w;
        cp_wait0();
        __syncthreads();
    }

    for (int it = 0; it < NT; it++) {
        const int buf = it & 1;
        float4 av0 = make_float4(0.f, 0.f, 0.f, 0.f);
        float4 av1 = make_float4(0.f, 0.f, 0.f, 0.f);
        bool more = (it + 1 < NT);
        if (more) {
            int k0n = (it + 1) * 16;
            const float* arow = dw + (m0 + am) * K2G + k0n + ak;
            if (k0n + ak + 4 <= K2G)
                av0 = *reinterpret_cast<const float4*>(arow);
            if (k0n + ak + 8 <= K2G)
                av1 = *reinterpret_cast<const float4*>(arow + 4);
            #pragma unroll
            for (int c = t; c < 1024; c += 256) {
                int kk = c >> 6, pos = (c & 63) * 4;
                int sz = (k0n + kk < K2G) ? 16 : 0;
                uint32_t dst = (uint32_t)__cvta_generic_to_shared(&Bs[buf ^ 1][kk][pos]);
                cp_async16(dst, xcb + (size_t)(k0n + kk) * THW + n0 + pos, sz);
            }
            cp_commit();
        }

        #pragma unroll
        for (int kk = 0; kk < 16; kk++) {
            float4 a0 = *reinterpret_cast<const float4*>(&As[buf][kk][ty * 8]);
            float4 a1 = *reinterpret_cast<const float4*>(&As[buf][kk][ty * 8 + 4]);
            ulonglong2 b0 = *reinterpret_cast<const ulonglong2*>(&Bs[buf][kk][tx * 4]);
            ulonglong2 b1 = *reinterpret_cast<const ulonglong2*>(&Bs[buf][kk][tx * 4 + 64]);
            ulonglong2 b2 = *reinterpret_cast<const ulonglong2*>(&Bs[buf][kk][tx * 4 + 128]);
            ulonglong2 b3 = *reinterpret_cast<const ulonglong2*>(&Bs[buf][kk][tx * 4 + 192]);
            float am8[8] = {a0.x, a0.y, a0.z, a0.w, a1.x, a1.y, a1.z, a1.w};
            #pragma unroll
            for (int i = 0; i < 8; i++) {
                ull a2 = pack2(am8[i]);
                ffma2(acc[i][0], a2, b0.x); ffma2(acc[i][1], a2, b0.y);
                ffma2(acc[i][2], a2, b1.x); ffma2(acc[i][3], a2, b1.y);
                ffma2(acc[i][4], a2, b2.x); ffma2(acc[i][5], a2, b2.y);
                ffma2(acc[i][6], a2, b3.x); ffma2(acc[i][7], a2, b3.y);
            }
        }

        if (more) {
            As[buf ^ 1][ak + 0][am] = av0.x; As[buf ^ 1][ak + 1][am] = av0.y;
            As[buf ^ 1][ak + 2][am] = av0.z; As[buf ^ 1][ak + 3][am] = av0.w;
            As[buf ^ 1][ak + 4][am] = av1.x; As[buf ^ 1][ak + 5][am] = av1.y;
            As[buf ^ 1][ak + 6][am] = av1.z; As[buf ^ 1][ak + 7][am] = av1.w;
        }
        cp_wait0();
        __syncthreads();
    }

    // Epilogue: BN + residual + ReLU
    #pragma unroll
    for (int i = 0; i < 8; i++) {
        int o = m0 + ty * 8 + i;
        float inv  = dg[o] * rsqrtf(dv[o] + EPSI);
        float bias = db[o] - dm[o] * inv;
        const float* xr = x + (size_t)b * Cc * THW + (size_t)o * THW + n0;
        float*       op = out + (size_t)b * Cc * THW + (size_t)o * THW + n0;
        #pragma unroll
        for (int j = 0; j < 4; j++) {
            float2 v0 = unpack2(acc[i][2 * j]);
            float2 v1 = unpack2(acc[i][2 * j + 1]);
            float4 rv = *reinterpret_cast<const float4*>(xr + tx * 4 + 64 * j);
            float4 r;
            r.x = fmaxf(v0.x * inv + bias + rv.x, 0.f);
            r.y = fmaxf(v0.y * inv + bias + rv.y, 0.f);
            r.z = fmaxf(v1.x * inv + bias + rv.z, 0.f);
            r.w = fmaxf(v1.y * inv + bias + rv.w, 0.f);
            *reinterpret_cast<float4*>(op + tx * 4 + 64 * j) = r;
        }
    }
}

// ---------------------------------------------------------------------------
extern "C" void kernel_launch(void* const* d_in, const int* in_sizes, int n_in,
                              void* d_out, int out_size)
{
    const float* x     = (const float*)d_in[0];
    const float* enc_w = (const float*)d_in[1];
    const float* eg    = (const float*)d_in[2];
    const float* eb    = (const float*)d_in[3];
    const float* em    = (const float*)d_in[4];
    const float* ev    = (const float*)d_in[5];
    const float* fw    = (const float*)d_in[6];
    const float* dw    = (const float*)d_in[7];
    const float* dg    = (const float*)d_in[8];
    const float* db    = (const float*)d_in[9];
    const float* dm    = (const float*)d_in[10];
    const float* dv    = (const float*)d_in[11];
    float* out = (float*)d_out;

    dim3 g1(THW / 256, Bsz);
    enc_kernel<<<g1, 128>>>(x, enc_w, eg, eb, em, ev);

    dim3 g2(Hh / 4, Tt, Bsz * Gg);
    corr_kernel<<<g2, 224>>>(fw);

    dim3 g3(THW / 256, 2, Bsz);
    dec_kernel<<<g3, 256>>>(x, dw, dg, db, dm, dv, out);
}

// round 5
// speedup vs baseline: 2.0183x; 1.5707x over previous
#include <cuda_runtime.h>
#include <cstdint>

#define Bsz   4
#define Cc    256
#define CE    64
#define Tt    16
#define Hh    56
#define Ww    56
#define HW    3136
#define THW   50176
#define Gg    4
#define K2G   196
#define KPAD  224
#define EPSI  1e-5f

// Scratch (device globals: allocation-free rule)
__device__ float    g_xenc[(size_t)Bsz * CE * THW];
__device__ uint32_t g_xcorrt[(size_t)Bsz * THW * KPAD];   // [pixel][k'] tf32 bits
__device__ uint32_t g_dwt[Cc * KPAD];                     // dec_w permuted+rounded

typedef unsigned long long ull;

__device__ __forceinline__ void ffma2(ull& d, ull a, ull b) {
    asm("fma.rn.f32x2 %0, %1, %2, %0;" : "+l"(d) : "l"(a), "l"(b));
}
__device__ __forceinline__ ull pack2(float x) {
    ull r; unsigned u = __float_as_uint(x);
    asm("mov.b64 %0, {%1, %1};" : "=l"(r) : "r"(u));
    return r;
}
__device__ __forceinline__ float2 unpack2(ull v) {
    unsigned lo, hi;
    asm("mov.b64 {%0, %1}, %2;" : "=r"(lo), "=r"(hi) : "l"(v));
    return make_float2(__uint_as_float(lo), __uint_as_float(hi));
}
__device__ __forceinline__ void cp_async16(uint32_t smem_addr, const void* gptr, int src_bytes) {
    asm volatile("cp.async.cg.shared.global [%0], [%1], 16, %2;"
                 :: "r"(smem_addr), "l"(gptr), "r"(src_bytes));
}
__device__ __forceinline__ void cp_commit() { asm volatile("cp.async.commit_group;"); }
__device__ __forceinline__ void cp_wait0()  { asm volatile("cp.async.wait_group 0;"); }
__device__ __forceinline__ void cp_wait1()  { asm volatile("cp.async.wait_group 1;"); }

__device__ __forceinline__ uint32_t tf32rna(float f) {
    uint32_t r; asm("cvt.rna.tf32.f32 %0, %1;" : "=r"(r) : "f"(f)); return r;
}
__device__ __forceinline__ uint32_t smem_u32(const void* p) {
    return (uint32_t)__cvta_generic_to_shared(p);
}

// warp-level tensor-core mma (base PTX, sm_80+): D += A*B, tf32 in, f32 acc
__device__ __forceinline__ void mma_tf32(float* c, const uint32_t* a, const uint32_t* b) {
    asm volatile(
        "mma.sync.aligned.m16n8k8.row.col.f32.tf32.tf32.f32 "
        "{%0,%1,%2,%3}, {%4,%5,%6,%7}, {%8,%9}, {%0,%1,%2,%3};"
        : "+f"(c[0]), "+f"(c[1]), "+f"(c[2]), "+f"(c[3])
        : "r"(a[0]), "r"(a[1]), "r"(a[2]), "r"(a[3]), "r"(b[0]), "r"(b[1]));
}

// ---------------------------------------------------------------------------
// Kernel 0: prep — permute + rna-round dec_w into g_dwt[m][g*49+tap], pad to 224
// ---------------------------------------------------------------------------
__global__ void prep_kernel(const float* __restrict__ dw)
{
    int idx = blockIdx.x * 256 + threadIdx.x;
    if (idx >= Cc * KPAD) return;
    int m = idx / KPAD, kp = idx % KPAD;
    uint32_t v = 0;
    if (kp < K2G) {
        int g = kp / 49, tap = kp % 49;
        v = tf32rna(dw[m * K2G + tap * 4 + g]);
    }
    g_dwt[idx] = v;
}

// ---------------------------------------------------------------------------
// Kernel 1: enc 1x1 conv (fp32 ffma path, unchanged)
// ---------------------------------------------------------------------------
__global__ void __launch_bounds__(128, 2) enc_kernel(
    const float* __restrict__ x, const float* __restrict__ w,
    const float* __restrict__ eg, const float* __restrict__ eb,
    const float* __restrict__ em, const float* __restrict__ ev)
{
    const int n0 = blockIdx.x * 256;
    const int b  = blockIdx.y;

    __shared__ float Bs[2][16][256];
    __shared__ float As[2][16][64];

    const int t  = threadIdx.x;
    const int tx = t & 15;
    const int ty = t >> 4;

    ull acc[8][8];
    #pragma unroll
    for (int i = 0; i < 8; i++)
        #pragma unroll
        for (int j = 0; j < 8; j++) acc[i][j] = 0ull;

    const float* xb = x + (size_t)b * Cc * THW;
    const int am = t >> 1;
    const int ak = (t & 1) * 8;
    const int NT = Cc / 16;

    {
        float4 av0 = *reinterpret_cast<const float4*>(w + am * Cc + ak);
        float4 av1 = *reinterpret_cast<const float4*>(w + am * Cc + ak + 4);
        #pragma unroll
        for (int c = t; c < 1024; c += 128) {
            int kk = c >> 6, pos = (c & 63) * 4;
            cp_async16(smem_u32(&Bs[0][kk][pos]), xb + (size_t)kk * THW + n0 + pos, 16);
        }
        cp_commit();
        As[0][ak + 0][am] = av0.x; As[0][ak + 1][am] = av0.y;
        As[0][ak + 2][am] = av0.z; As[0][ak + 3][am] = av0.w;
        As[0][ak + 4][am] = av1.x; As[0][ak + 5][am] = av1.y;
        As[0][ak + 6][am] = av1.z; As[0][ak + 7][am] = av1.w;
        cp_wait0();
        __syncthreads();
    }

    for (int it = 0; it < NT; it++) {
        const int buf = it & 1;
        float4 av0, av1;
        bool more = (it + 1 < NT);
        if (more) {
            int k0n = (it + 1) * 16;
            av0 = *reinterpret_cast<const float4*>(w + am * Cc + k0n + ak);
            av1 = *reinterpret_cast<const float4*>(w + am * Cc + k0n + ak + 4);
            #pragma unroll
            for (int c = t; c < 1024; c += 128) {
                int kk = c >> 6, pos = (c & 63) * 4;
                cp_async16(smem_u32(&Bs[buf ^ 1][kk][pos]),
                           xb + (size_t)(k0n + kk) * THW + n0 + pos, 16);
            }
            cp_commit();
        }

        #pragma unroll
        for (int kk = 0; kk < 16; kk++) {
            float4 a0 = *reinterpret_cast<const float4*>(&As[buf][kk][ty * 8]);
            float4 a1 = *reinterpret_cast<const float4*>(&As[buf][kk][ty * 8 + 4]);
            ulonglong2 b0 = *reinterpret_cast<const ulonglong2*>(&Bs[buf][kk][tx * 4]);
            ulonglong2 b1 = *reinterpret_cast<const ulonglong2*>(&Bs[buf][kk][tx * 4 + 64]);
            ulonglong2 b2 = *reinterpret_cast<const ulonglong2*>(&Bs[buf][kk][tx * 4 + 128]);
            ulonglong2 b3 = *reinterpret_cast<const ulonglong2*>(&Bs[buf][kk][tx * 4 + 192]);
            float am8[8] = {a0.x, a0.y, a0.z, a0.w, a1.x, a1.y, a1.z, a1.w};
            #pragma unroll
            for (int i = 0; i < 8; i++) {
                ull a2 = pack2(am8[i]);
                ffma2(acc[i][0], a2, b0.x); ffma2(acc[i][1], a2, b0.y);
                ffma2(acc[i][2], a2, b1.x); ffma2(acc[i][3], a2, b1.y);
                ffma2(acc[i][4], a2, b2.x); ffma2(acc[i][5], a2, b2.y);
                ffma2(acc[i][6], a2, b3.x); ffma2(acc[i][7], a2, b3.y);
            }
        }

        if (more) {
            As[buf ^ 1][ak + 0][am] = av0.x; As[buf ^ 1][ak + 1][am] = av0.y;
            As[buf ^ 1][ak + 2][am] = av0.z; As[buf ^ 1][ak + 3][am] = av0.w;
            As[buf ^ 1][ak + 4][am] = av1.x; As[buf ^ 1][ak + 5][am] = av1.y;
            As[buf ^ 1][ak + 6][am] = av1.z; As[buf ^ 1][ak + 7][am] = av1.w;
        }
        cp_wait0();
        __syncthreads();
    }

    #pragma unroll
    for (int i = 0; i < 8; i++) {
        int ce = ty * 8 + i;
        float inv  = eg[ce] * rsqrtf(ev[ce] + EPSI);
        float bias = eb[ce] - em[ce] * inv;
        float* op = g_xenc + (size_t)b * CE * THW + (size_t)ce * THW + n0;
        #pragma unroll
        for (int j = 0; j < 4; j++) {
            float2 v0 = unpack2(acc[i][2 * j]);
            float2 v1 = unpack2(acc[i][2 * j + 1]);
            float4 r;
            r.x = fmaxf(v0.x * inv + bias, 0.f);
            r.y = fmaxf(v0.y * inv + bias, 0.f);
            r.z = fmaxf(v1.x * inv + bias, 0.f);
            r.w = fmaxf(v1.y * inv + bias, 0.f);
            *reinterpret_cast<float4*>(op + tx * 4 + 64 * j) = r;
        }
    }
}

// ---------------------------------------------------------------------------
// Kernel 2: weighted correlation -> transposed tf32 output
// g_xcorrt[pixel][g*49+tap], pixel = b*THW + t*HW + h*56 + w, K padded to 224
// ---------------------------------------------------------------------------
__global__ void __launch_bounds__(224) corr_kernel(const float* __restrict__ fw)
{
    const int h0 = blockIdx.x * 4;
    const int tt = blockIdx.y;
    const int b  = blockIdx.z >> 2;
    const int g  = blockIdx.z & 3;

    __shared__ float sbuf[11008];
    float (*x1s)[4][56]  = reinterpret_cast<float (*)[4][56]>(sbuf);
    float (*x2s)[10][62] = reinterpret_cast<float (*)[10][62]>(sbuf + 1792);
    float (*ws)[49]      = reinterpret_cast<float (*)[49]>(sbuf + 6752);
    uint32_t* stage      = reinterpret_cast<uint32_t*>(sbuf);

    const int tid = threadIdx.x;
    const int py = tid / 56;
    const int px = tid % 56;

    float acc[49];
    #pragma unroll
    for (int i = 0; i < 49; i++) acc[i] = 0.f;

    const int t1 = (tt == 0) ? 0 : tt - 1;
    const float* x1base = g_xenc + (size_t)b * CE * THW + (size_t)t1 * HW;
    const float* x2base = g_xenc + (size_t)b * CE * THW + (size_t)tt * HW;

    for (int chunk = 0; chunk < 2; chunk++) {
        const int ce0 = g * 16 + chunk * 8;

        for (int i = tid; i < 8 * 49; i += 224) {
            int ce = i / 49, tap = i % 49;
            ws[ce][tap] = fw[((size_t)(ce0 + ce) * Tt + tt) * 49 + tap];
        }
        #pragma unroll
        for (int ce = 0; ce < 8; ce++) {
            x1s[ce][py][px] =
                x1base[(size_t)(ce0 + ce) * THW + (h0 + py) * Ww + px];
        }
        for (int i = tid; i < 8 * 620; i += 224) {
            int ce = i / 620, p = i % 620;
            int r = p / 62, c = p % 62;
            int hy = h0 + r - 3, wx = c - 3;
            float v = 0.f;
            if (hy >= 0 && hy < Hh && wx >= 0 && wx < Ww)
                v = x2base[(size_t)(ce0 + ce) * THW + hy * Ww + wx];
            x2s[ce][r][c] = v;
        }
        __syncthreads();

        for (int ce = 0; ce < 8; ce++) {
            float x1v = x1s[ce][py][px];
            #pragma unroll
            for (int ky = 0; ky < 7; ky++) {
                #pragma unroll
                for (int kx = 0; kx < 7; kx++) {
                    acc[ky * 7 + kx] +=
                        ws[ce][ky * 7 + kx] * x1v * x2s[ce][py + ky][px + kx];
                }
            }
        }
        __syncthreads();
    }

    #pragma unroll
    for (int tap = 0; tap < 49; tap++)
        stage[tid * 49 + tap] = tf32rna(acc[tap] * (1.f / 16.f));
    __syncthreads();

    const int wid = tid >> 5, lid = tid & 31;
    const size_t pixbase = (size_t)b * THW + (size_t)tt * HW + (size_t)h0 * Ww;
    for (int i = 0; i < 32; i++) {
        int r = wid * 32 + i;
        size_t pixel = pixbase + r;
        uint32_t* orow = g_xcorrt + pixel * KPAD + g * 49;
        orow[lid] = stage[r * 49 + lid];
        if (lid < 17) orow[32 + lid] = stage[r * 49 + 32 + lid];
        if (g == 0 && lid < 28)
            g_xcorrt[pixel * KPAD + 196 + lid] = 0u;
    }
}

// ---------------------------------------------------------------------------
// Kernel 3: dec GEMM on warp-level mma.sync (tf32 legacy tensor path).
// BM=128, BN=128, 256 thr = 8 warps (2m x 4n), warp tile 64x32, m16n8k8.
// K-chunks of 32, double-buffered cp.async, XOR-swizzled 128B smem rows.
// ---------------------------------------------------------------------------
#define D_SMEM (4 * 16384)   // A[2][128][32] + B[2][128][32] floats = 64 KB

// swizzled float offset for (row, k) in a [rows][32] tile
__device__ __forceinline__ int swoff(int r, int k) {
    return r * 32 + ((((k >> 2) ^ r) & 7) << 2) + (k & 3);
}

__global__ void __launch_bounds__(256) dec_kernel(
    const float* __restrict__ x,
    const float* __restrict__ dg, const float* __restrict__ db,
    const float* __restrict__ dm, const float* __restrict__ dv,
    float* __restrict__ out)
{
    extern __shared__ char dsm[];
    const int t    = threadIdx.x;
    const int wid  = t >> 5, lane = t & 31;
    const int warpM = wid >> 2;          // 0..1
    const int warpN = wid & 3;           // 0..3

    const int nx = blockIdx.x;           // 392 n-tiles of 128 per batch
    const int m0 = blockIdx.y * 128;     // 0 or 128
    const int b  = blockIdx.z;

    const uint32_t* arow = g_dwt + (size_t)m0 * KPAD;
    const uint32_t* brow = g_xcorrt + ((size_t)b * THW + (size_t)nx * 128) * KPAD;

    float cacc[4][4][4];                 // [mt][nt][reg]
    #pragma unroll
    for (int i = 0; i < 4; i++)
        #pragma unroll
        for (int j = 0; j < 4; j++)
            #pragma unroll
            for (int r = 0; r < 4; r++) cacc[i][j][r] = 0.f;

    // chunk loader: A 128x32 floats (16KB) at dsm + buf*16KB,
    //               B 128x32 floats (16KB) at dsm + 32KB + buf*16KB
    auto load_chunk = [&](int kc, int buf) {
        char* Ab = dsm + buf * 16384;
        char* Bb = dsm + 32768 + buf * 16384;
        #pragma unroll
        for (int i = 0; i < 4; i++) {
            int e = t + 256 * i;         // 0..1023
            int row = e >> 3, c = e & 7;
            uint32_t soff = row * 128 + (((c ^ row) & 7) * 16);
            cp_async16(smem_u32(Ab + soff), arow + (size_t)row * KPAD + kc * 32 + c * 4, 16);
            cp_async16(smem_u32(Bb + soff), brow + (size_t)row * KPAD + kc * 32 + c * 4, 16);
        }
    };

    load_chunk(0, 0);
    cp_commit();

    for (int c = 0; c < 7; c++) {
        const int buf = c & 1;
        if (c + 1 < 7) {
            load_chunk(c + 1, buf ^ 1);
            cp_commit();
            cp_wait1();
        } else {
            cp_wait0();
        }
        __syncthreads();

        const float* Ab = reinterpret_cast<const float*>(dsm + buf * 16384);
        const float* Bb = reinterpret_cast<const float*>(dsm + 32768 + buf * 16384);

        #pragma unroll
        for (int ks = 0; ks < 4; ks++) {
            const int kb = ks * 8;
            const int kf = kb + (lane & 3);

            uint32_t afr[4][4];
            #pragma unroll
            for (int mt = 0; mt < 4; mt++) {
                int r = warpM * 64 + mt * 16 + (lane >> 2);
                afr[mt][0] = __float_as_uint(Ab[swoff(r,     kf)]);
                afr[mt][1] = __float_as_uint(Ab[swoff(r + 8, kf)]);
                afr[mt][2] = __float_as_uint(Ab[swoff(r,     kf + 4)]);
                afr[mt][3] = __float_as_uint(Ab[swoff(r + 8, kf + 4)]);
            }
            uint32_t bfr[4][2];
            #pragma unroll
            for (int nt = 0; nt < 4; nt++) {
                int n = warpN * 32 + nt * 8 + (lane >> 2);
                bfr[nt][0] = __float_as_uint(Bb[swoff(n, kf)]);
                bfr[nt][1] = __float_as_uint(Bb[swoff(n, kf + 4)]);
            }
            #pragma unroll
            for (int mt = 0; mt < 4; mt++)
                #pragma unroll
                for (int nt = 0; nt < 4; nt++)
                    mma_tf32(cacc[mt][nt], afr[mt], bfr[nt]);
        }
        __syncthreads();
    }

    // Epilogue: BN + residual + ReLU (float2 stores)
    const size_t nbase = (size_t)nx * 128;
    #pragma unroll
    for (int mt = 0; mt < 4; mt++) {
        int mrow = m0 + warpM * 64 + mt * 16 + (lane >> 2);
        float inv0  = dg[mrow] * rsqrtf(dv[mrow] + EPSI);
        float bias0 = db[mrow] - dm[mrow] * inv0;
        float inv1  = dg[mrow + 8] * rsqrtf(dv[mrow + 8] + EPSI);
        float bias1 = db[mrow + 8] - dm[mrow + 8] * inv1;
        const float* xr0 = x   + ((size_t)b * Cc + mrow)     * THW + nbase;
        const float* xr1 = x   + ((size_t)b * Cc + mrow + 8) * THW + nbase;
        float*       op0 = out + ((size_t)b * Cc + mrow)     * THW + nbase;
        float*       op1 = out + ((size_t)b * Cc + mrow + 8) * THW + nbase;
        #pragma unroll
        for (int nt = 0; nt < 4; nt++) {
            int n = warpN * 32 + nt * 8 + (lane & 3) * 2;
            float2 r0 = *reinterpret_cast<const float2*>(xr0 + n);
            float2 r1 = *reinterpret_cast<const float2*>(xr1 + n);
            float2 o0, o1;
            o0.x = fmaxf(cacc[mt][nt][0] * inv0 + bias0 + r0.x, 0.f);
            o0.y = fmaxf(cacc[mt][nt][1] * inv0 + bias0 + r0.y, 0.f);
            o1.x = fmaxf(cacc[mt][nt][2] * inv1 + bias1 + r1.x, 0.f);
            o1.y = fmaxf(cacc[mt][nt][3] * inv1 + bias1 + r1.y, 0.f);
            *reinterpret_cast<float2*>(op0 + n) = o0;
            *reinterpret_cast<float2*>(op1 + n) = o1;
        }
    }
}

// ---------------------------------------------------------------------------
extern "C" void kernel_launch(void* const* d_in, const int* in_sizes, int n_in,
                              void* d_out, int out_size)
{
    const float* x     = (const float*)d_in[0];
    const float* enc_w = (const float*)d_in[1];
    const float* eg    = (const float*)d_in[2];
    const float* eb    = (const float*)d_in[3];
    const float* em    = (const float*)d_in[4];
    const float* ev    = (const float*)d_in[5];
    const float* fw    = (const float*)d_in[6];
    const float* dw    = (const float*)d_in[7];
    const float* dg    = (const float*)d_in[8];
    const float* db    = (const float*)d_in[9];
    const float* dm    = (const float*)d_in[10];
    const float* dv    = (const float*)d_in[11];
    float* out = (float*)d_out;

    cudaFuncSetAttribute(dec_kernel,
                         cudaFuncAttributeMaxDynamicSharedMemorySize, D_SMEM);

    prep_kernel<<<(Cc * KPAD + 255) / 256, 256>>>(dw);

    dim3 g1(THW / 256, Bsz);
    enc_kernel<<<g1, 128>>>(x, enc_w, eg, eb, em, ev);

    dim3 g2(Hh / 4, Tt, Bsz * Gg);
    corr_kernel<<<g2, 224>>>(fw);

    dim3 g3(THW / 128, 2, Bsz);
    dec_kernel<<<g3, 256, D_SMEM>>>(x, dg, db, dm, dv, out);
}

// round 6
// speedup vs baseline: 2.1684x; 1.0743x over previous
#include <cuda_runtime.h>
#include <cstdint>

#define Bsz   4
#define Cc    256
#define CE    64
#define Tt    16
#define Hh    56
#define Ww    56
#define HW    3136
#define THW   50176
#define Gg    4
#define K2G   196
#define KPAD  224
#define EPSI  1e-5f

// Scratch (device globals: allocation-free rule)
__device__ float    g_xenc[(size_t)Bsz * CE * THW];
__device__ uint32_t g_xcorrt[(size_t)Bsz * THW * KPAD];   // [pixel][k'] tf32 bits
__device__ uint32_t g_dwt[Cc * KPAD];                     // dec_w permuted+rounded
__device__ uint32_t g_wt[CE * Cc];                        // enc_w rounded

__device__ __forceinline__ void cp_async16(uint32_t smem_addr, const void* gptr, int src_bytes) {
    asm volatile("cp.async.cg.shared.global [%0], [%1], 16, %2;"
                 :: "r"(smem_addr), "l"(gptr), "r"(src_bytes));
}
__device__ __forceinline__ void cp_commit() { asm volatile("cp.async.commit_group;"); }
__device__ __forceinline__ void cp_wait0()  { asm volatile("cp.async.wait_group 0;"); }
__device__ __forceinline__ void cp_wait1()  { asm volatile("cp.async.wait_group 1;"); }
__device__ __forceinline__ void cp_wait2()  { asm volatile("cp.async.wait_group 2;"); }

__device__ __forceinline__ uint32_t tf32rna(float f) {
    uint32_t r; asm("cvt.rna.tf32.f32 %0, %1;" : "=r"(r) : "f"(f)); return r;
}
__device__ __forceinline__ uint32_t smem_u32(const void* p) {
    return (uint32_t)__cvta_generic_to_shared(p);
}
__device__ __forceinline__ void mma_tf32(float* c, const uint32_t* a, const uint32_t* b) {
    asm volatile(
        "mma.sync.aligned.m16n8k8.row.col.f32.tf32.tf32.f32 "
        "{%0,%1,%2,%3}, {%4,%5,%6,%7}, {%8,%9}, {%0,%1,%2,%3};"
        : "+f"(c[0]), "+f"(c[1]), "+f"(c[2]), "+f"(c[3])
        : "r"(a[0]), "r"(a[1]), "r"(a[2]), "r"(a[3]), "r"(b[0]), "r"(b[1]));
}
// swizzled float offset for (row, k) in a [rows][32] k-contiguous tile
__device__ __forceinline__ int swoff(int r, int k) {
    return r * 32 + ((((k >> 2) ^ r) & 7) << 2) + (k & 3);
}

// ---------------------------------------------------------------------------
// Kernel 0: prep — round dec_w (permuted, padded) and enc_w to tf32 bits
// ---------------------------------------------------------------------------
__global__ void prep_kernel(const float* __restrict__ dw, const float* __restrict__ ew)
{
    int idx = blockIdx.x * 256 + threadIdx.x;
    if (idx < Cc * KPAD) {
        int m = idx / KPAD, kp = idx % KPAD;
        uint32_t v = 0;
        if (kp < K2G) {
            int g = kp / 49, tap = kp % 49;
            v = tf32rna(dw[m * K2G + tap * 4 + g]);
        }
        g_dwt[idx] = v;
    } else if (idx < Cc * KPAD + CE * Cc) {
        int j = idx - Cc * KPAD;
        g_wt[j] = tf32rna(ew[j]);
    }
}

// ---------------------------------------------------------------------------
// Kernel 1: enc 1x1 conv on mma.sync tf32.
// C[64 ce][256 pix] per CTA. A = g_wt [64][256] (pre-rounded, dec-style
// swizzled tile). B = x [c][pix] staged k-major [32k][256n] with per-k-row
// chunk-XOR swizzle (j ^= 2*(k&3)) -> conflict-free B frags; cvt.rna on load.
// 8 warps, warp tile 64m x 32n. 2-stage cp.async.
// ---------------------------------------------------------------------------
#define E_SMEM (2 * (8192 + 32768))   // 81920
#define E_AST(s) ((s) * 8192)
#define E_BST(s) (16384 + (s) * 32768)

__global__ void __launch_bounds__(256, 2) enc_kernel(
    const float* __restrict__ x,
    const float* __restrict__ eg, const float* __restrict__ eb,
    const float* __restrict__ em, const float* __restrict__ ev)
{
    extern __shared__ char esm[];
    const int t = threadIdx.x;
    const int wid = t >> 5, lane = t & 31;
    const int warpN = wid;                 // 0..7, 32 n each
    const int n0 = blockIdx.x * 256;
    const int b  = blockIdx.y;

    const float* xb = x + (size_t)b * Cc * THW;

    float cacc[4][4][4];
    #pragma unroll
    for (int i = 0; i < 4; i++)
        #pragma unroll
        for (int j = 0; j < 4; j++)
            #pragma unroll
            for (int r = 0; r < 4; r++) cacc[i][j][r] = 0.f;

    // loop-invariant B positions per lane (within a k-row of 256 floats)
    int bpos[4];
    #pragma unroll
    for (int nt = 0; nt < 4; nt++) {
        int n = warpN * 32 + nt * 8 + (lane >> 2);
        bpos[nt] = (((n >> 2) ^ (2 * (lane & 3))) << 2) + (n & 3);
    }

    auto load_chunk = [&](int kc, int s) {
        // A: 64 rows x 8 16B-chunks
        {
            int e = t, r = e >> 3, c = e & 7;
            cp_async16(smem_u32(esm + E_AST(s) + r * 128 + (((c ^ r) & 7) << 4)),
                       g_wt + r * Cc + kc * 32 + c * 4, 16);
            e = t + 256; r = e >> 3; c = e & 7;
            cp_async16(smem_u32(esm + E_AST(s) + r * 128 + (((c ^ r) & 7) << 4)),
                       g_wt + r * Cc + kc * 32 + c * 4, 16);
        }
        // B: 32 k-rows x 64 16B-chunks, chunk-XOR swizzle
        #pragma unroll
        for (int i = 0; i < 8; i++) {
            int e = t + 256 * i;
            int k = e >> 6, j = e & 63;
            uint32_t dst = smem_u32(esm + E_BST(s) + k * 1024
                                    + ((j ^ (2 * (k & 3))) << 4));
            cp_async16(dst, xb + (size_t)(kc * 32 + k) * THW + n0 + j * 4, 16);
        }
    };

    load_chunk(0, 0);
    cp_commit();

    for (int c = 0; c < 8; c++) {
        const int s = c & 1;
        if (c > 0) __syncthreads();
        if (c + 1 < 8) { load_chunk(c + 1, s ^ 1); cp_commit(); cp_wait1(); }
        else cp_wait0();
        __syncthreads();

        const uint32_t* Ab = reinterpret_cast<const uint32_t*>(esm + E_AST(s));
        const uint32_t* Bb = reinterpret_cast<const uint32_t*>(esm + E_BST(s));

        #pragma unroll
        for (int ks = 0; ks < 4; ks++) {
            const int kf = ks * 8 + (lane & 3);
            uint32_t bfr[4][2];
            #pragma unroll
            for (int nt = 0; nt < 4; nt++) {
                bfr[nt][0] = tf32rna(__uint_as_float(Bb[kf * 256 + bpos[nt]]));
                bfr[nt][1] = tf32rna(__uint_as_float(Bb[(kf + 4) * 256 + bpos[nt]]));
            }
            #pragma unroll
            for (int mt = 0; mt < 4; mt++) {
                int r = mt * 16 + (lane >> 2);
                uint32_t afr[4];
                afr[0] = Ab[swoff(r,     kf)];
                afr[1] = Ab[swoff(r + 8, kf)];
                afr[2] = Ab[swoff(r,     kf + 4)];
                afr[3] = Ab[swoff(r + 8, kf + 4)];
                #pragma unroll
                for (int nt = 0; nt < 4; nt++)
                    mma_tf32(cacc[mt][nt], afr, bfr[nt]);
            }
        }
    }

    // Epilogue: BN + ReLU -> g_xenc[ce][pixel]
    #pragma unroll
    for (int mt = 0; mt < 4; mt++) {
        int ce0 = mt * 16 + (lane >> 2);
        float inv0  = eg[ce0] * rsqrtf(ev[ce0] + EPSI);
        float bias0 = eb[ce0] - em[ce0] * inv0;
        float inv1  = eg[ce0 + 8] * rsqrtf(ev[ce0 + 8] + EPSI);
        float bias1 = eb[ce0 + 8] - em[ce0 + 8] * inv1;
        float* op0 = g_xenc + ((size_t)b * CE + ce0)     * THW + n0;
        float* op1 = g_xenc + ((size_t)b * CE + ce0 + 8) * THW + n0;
        #pragma unroll
        for (int nt = 0; nt < 4; nt++) {
            int n = warpN * 32 + nt * 8 + (lane & 3) * 2;
            float2 o0, o1;
            o0.x = fmaxf(cacc[mt][nt][0] * inv0 + bias0, 0.f);
            o0.y = fmaxf(cacc[mt][nt][1] * inv0 + bias0, 0.f);
            o1.x = fmaxf(cacc[mt][nt][2] * inv1 + bias1, 0.f);
            o1.y = fmaxf(cacc[mt][nt][3] * inv1 + bias1, 0.f);
            *reinterpret_cast<float2*>(op0 + n) = o0;
            *reinterpret_cast<float2*>(op1 + n) = o1;
        }
    }
}

// ---------------------------------------------------------------------------
// Kernel 2: weighted correlation -> transposed tf32 output (unchanged)
// ---------------------------------------------------------------------------
__global__ void __launch_bounds__(224) corr_kernel(const float* __restrict__ fw)
{
    const int h0 = blockIdx.x * 4;
    const int tt = blockIdx.y;
    const int b  = blockIdx.z >> 2;
    const int g  = blockIdx.z & 3;

    __shared__ float sbuf[11008];
    float (*x1s)[4][56]  = reinterpret_cast<float (*)[4][56]>(sbuf);
    float (*x2s)[10][62] = reinterpret_cast<float (*)[10][62]>(sbuf + 1792);
    float (*ws)[49]      = reinterpret_cast<float (*)[49]>(sbuf + 6752);
    uint32_t* stage      = reinterpret_cast<uint32_t*>(sbuf);

    const int tid = threadIdx.x;
    const int py = tid / 56;
    const int px = tid % 56;

    float acc[49];
    #pragma unroll
    for (int i = 0; i < 49; i++) acc[i] = 0.f;

    const int t1 = (tt == 0) ? 0 : tt - 1;
    const float* x1base = g_xenc + (size_t)b * CE * THW + (size_t)t1 * HW;
    const float* x2base = g_xenc + (size_t)b * CE * THW + (size_t)tt * HW;

    for (int chunk = 0; chunk < 2; chunk++) {
        const int ce0 = g * 16 + chunk * 8;

        for (int i = tid; i < 8 * 49; i += 224) {
            int ce = i / 49, tap = i % 49;
            ws[ce][tap] = fw[((size_t)(ce0 + ce) * Tt + tt) * 49 + tap];
        }
        #pragma unroll
        for (int ce = 0; ce < 8; ce++) {
            x1s[ce][py][px] =
                x1base[(size_t)(ce0 + ce) * THW + (h0 + py) * Ww + px];
        }
        for (int i = tid; i < 8 * 620; i += 224) {
            int ce = i / 620, p = i % 620;
            int r = p / 62, c = p % 62;
            int hy = h0 + r - 3, wx = c - 3;
            float v = 0.f;
            if (hy >= 0 && hy < Hh && wx >= 0 && wx < Ww)
                v = x2base[(size_t)(ce0 + ce) * THW + hy * Ww + wx];
            x2s[ce][r][c] = v;
        }
        __syncthreads();

        for (int ce = 0; ce < 8; ce++) {
            float x1v = x1s[ce][py][px];
            #pragma unroll
            for (int ky = 0; ky < 7; ky++) {
                #pragma unroll
                for (int kx = 0; kx < 7; kx++) {
                    acc[ky * 7 + kx] +=
                        ws[ce][ky * 7 + kx] * x1v * x2s[ce][py + ky][px + kx];
                }
            }
        }
        __syncthreads();
    }

    #pragma unroll
    for (int tap = 0; tap < 49; tap++)
        stage[tid * 49 + tap] = tf32rna(acc[tap] * (1.f / 16.f));
    __syncthreads();

    const int wid = tid >> 5, lid = tid & 31;
    const size_t pixbase = (size_t)b * THW + (size_t)tt * HW + (size_t)h0 * Ww;
    for (int i = 0; i < 32; i++) {
        int r = wid * 32 + i;
        size_t pixel = pixbase + r;
        uint32_t* orow = g_xcorrt + pixel * KPAD + g * 49;
        orow[lid] = stage[r * 49 + lid];
        if (lid < 17) orow[32 + lid] = stage[r * 49 + 32 + lid];
        if (g == 0 && lid < 28)
            g_xcorrt[pixel * KPAD + 196 + lid] = 0u;
    }
}

// ---------------------------------------------------------------------------
// Kernel 3: dec GEMM on mma.sync tf32, BM=256 (single m-tile -> B read once).
// BN=128, 256 thr = 8 warps (4m x 2n), warp tile 64x64, 3-stage cp.async.
// ---------------------------------------------------------------------------
#define D_SMEM (3 * (32768 + 16384))   // 147456
#define D_AST(s) ((s) * 32768)
#define D_BST(s) (98304 + (s) * 16384)

__global__ void __launch_bounds__(256, 1) dec_kernel(
    const float* __restrict__ x,
    const float* __restrict__ dg, const float* __restrict__ db,
    const float* __restrict__ dm, const float* __restrict__ dv,
    float* __restrict__ out)
{
    extern __shared__ char dsm[];
    const int t = threadIdx.x;
    const int wid = t >> 5, lane = t & 31;
    const int warpM = wid >> 1;            // 0..3 (64 m each)
    const int warpN = wid & 1;             // 0..1 (64 n each)

    const int nx = blockIdx.x;             // 392 n-tiles of 128
    const int b  = blockIdx.y;

    const uint32_t* brow = g_xcorrt + ((size_t)b * THW + (size_t)nx * 128) * KPAD;

    float cacc[4][8][4];
    #pragma unroll
    for (int i = 0; i < 4; i++)
        #pragma unroll
        for (int j = 0; j < 8; j++)
            #pragma unroll
            for (int r = 0; r < 4; r++) cacc[i][j][r] = 0.f;

    auto load_chunk = [&](int kc, int s) {
        #pragma unroll
        for (int i = 0; i < 8; i++) {      // A: 256 rows x 8 chunks
            int e = t + 256 * i;
            int r = e >> 3, c = e & 7;
            cp_async16(smem_u32(dsm + D_AST(s) + r * 128 + (((c ^ r) & 7) << 4)),
                       g_dwt + (size_t)r * KPAD + kc * 32 + c * 4, 16);
        }
        #pragma unroll
        for (int i = 0; i < 4; i++) {      // B: 128 rows x 8 chunks
            int e = t + 256 * i;
            int r = e >> 3, c = e & 7;
            cp_async16(smem_u32(dsm + D_BST(s) + r * 128 + (((c ^ r) & 7) << 4)),
                       brow + (size_t)r * KPAD + kc * 32 + c * 4, 16);
        }
    };

    load_chunk(0, 0); cp_commit();
    load_chunk(1, 1); cp_commit();

    for (int c = 0; c < 7; c++) {
        const int s = c % 3;
        if (c > 0) __syncthreads();
        if (c + 2 < 7) { load_chunk(c + 2, (c + 2) % 3); cp_commit(); }
        if (c < 5) cp_wait2(); else if (c == 5) cp_wait1(); else cp_wait0();
        __syncthreads();

        const uint32_t* Ab = reinterpret_cast<const uint32_t*>(dsm + D_AST(s));
        const uint32_t* Bb = reinterpret_cast<const uint32_t*>(dsm + D_BST(s));

        #pragma unroll
        for (int ks = 0; ks < 4; ks++) {
            const int kf = ks * 8 + (lane & 3);
            uint32_t bfr[8][2];
            #pragma unroll
            for (int nt = 0; nt < 8; nt++) {
                int n = warpN * 64 + nt * 8 + (lane >> 2);
                bfr[nt][0] = Bb[swoff(n, kf)];
                bfr[nt][1] = Bb[swoff(n, kf + 4)];
            }
            #pragma unroll
            for (int mt = 0; mt < 4; mt++) {
                int r = warpM * 64 + mt * 16 + (lane >> 2);
                uint32_t afr[4];
                afr[0] = Ab[swoff(r,     kf)];
                afr[1] = Ab[swoff(r + 8, kf)];
                afr[2] = Ab[swoff(r,     kf + 4)];
                afr[3] = Ab[swoff(r + 8, kf + 4)];
                #pragma unroll
                for (int nt = 0; nt < 8; nt++)
                    mma_tf32(cacc[mt][nt], afr, bfr[nt]);
            }
        }
    }

    // Epilogue: BN + residual + ReLU
    const size_t nbase = (size_t)nx * 128;
    #pragma unroll
    for (int mt = 0; mt < 4; mt++) {
        int mrow = warpM * 64 + mt * 16 + (lane >> 2);
        float inv0  = dg[mrow] * rsqrtf(dv[mrow] + EPSI);
        float bias0 = db[mrow] - dm[mrow] * inv0;
        float inv1  = dg[mrow + 8] * rsqrtf(dv[mrow + 8] + EPSI);
        float bias1 = db[mrow + 8] - dm[mrow + 8] * inv1;
        const float* xr0 = x   + ((size_t)b * Cc + mrow)     * THW + nbase;
        const float* xr1 = x   + ((size_t)b * Cc + mrow + 8) * THW + nbase;
        float*       op0 = out + ((size_t)b * Cc + mrow)     * THW + nbase;
        float*       op1 = out + ((size_t)b * Cc + mrow + 8) * THW + nbase;
        #pragma unroll
        for (int nt = 0; nt < 8; nt++) {
            int n = warpN * 64 + nt * 8 + (lane & 3) * 2;
            float2 r0 = *reinterpret_cast<const float2*>(xr0 + n);
            float2 r1 = *reinterpret_cast<const float2*>(xr1 + n);
            float2 o0, o1;
            o0.x = fmaxf(cacc[mt][nt][0] * inv0 + bias0 + r0.x, 0.f);
            o0.y = fmaxf(cacc[mt][nt][1] * inv0 + bias0 + r0.y, 0.f);
            o1.x = fmaxf(cacc[mt][nt][2] * inv1 + bias1 + r1.x, 0.f);
            o1.y = fmaxf(cacc[mt][nt][3] * inv1 + bias1 + r1.y, 0.f);
            *reinterpret_cast<float2*>(op0 + n) = o0;
            *reinterpret_cast<float2*>(op1 + n) = o1;
        }
    }
}

// ---------------------------------------------------------------------------
extern "C" void kernel_launch(void* const* d_in, const int* in_sizes, int n_in,
                              void* d_out, int out_size)
{
    const float* x     = (const float*)d_in[0];
    const float* enc_w = (const float*)d_in[1];
    const float* eg    = (const float*)d_in[2];
    const float* eb    = (const float*)d_in[3];
    const float* em    = (const float*)d_in[4];
    const float* ev    = (const float*)d_in[5];
    const float* fw    = (const float*)d_in[6];
    const float* dw    = (const float*)d_in[7];
    const float* dg    = (const float*)d_in[8];
    const float* db    = (const float*)d_in[9];
    const float* dm    = (const float*)d_in[10];
    const float* dv    = (const float*)d_in[11];
    float* out = (float*)d_out;

    cudaFuncSetAttribute(enc_kernel,
                         cudaFuncAttributeMaxDynamicSharedMemorySize, E_SMEM);
    cudaFuncSetAttribute(dec_kernel,
                         cudaFuncAttributeMaxDynamicSharedMemorySize, D_SMEM);

    int prep_n = Cc * KPAD + CE * Cc;
    prep_kernel<<<(prep_n + 255) / 256, 256>>>(dw, enc_w);

    dim3 g1(THW / 256, Bsz);
    enc_kernel<<<g1, 256, E_SMEM>>>(x, eg, eb, em, ev);

    dim3 g2(Hh / 4, Tt, Bsz * Gg);
    corr_kernel<<<g2, 224>>>(fw);

    dim3 g3(THW / 128, Bsz);
    dec_kernel<<<g3, 256, D_SMEM>>>(x, dg, db, dm, dv, out);
}